// round 12
// baseline (speedup 1.0000x reference)
#include <cuda_runtime.h>
#include <cuda_fp16.h>
#include <cstdint>

// ---------------------------------------------------------------------------
// Problem dims
// ---------------------------------------------------------------------------
#define B_BATCH 8
#define L_SEQ   256
#define D1      512
#define D2      512
#define KOUT    64
#define M1      (B_BATCH * L_SEQ)   // 2048 rows (b,i)

// ---------------------------------------------------------------------------
// Helpers (sm_80-era ISA only — harness PTX target is sm_103 without 'a')
// ---------------------------------------------------------------------------
__device__ __forceinline__ uint32_t smem_u32(const void* p) {
    uint32_t a;
    asm("{ .reg .u64 t; cvta.to.shared.u64 t, %1; cvt.u32.u64 %0, t; }"
        : "=r"(a) : "l"(p));
    return a;
}

__device__ __forceinline__ uint32_t swz128(uint32_t off) {  // 128B-row swizzle
    return off ^ ((off >> 3) & 0x70);
}

#define LDSM_X4(r0, r1, r2, r3, addr) \
    asm volatile("ldmatrix.sync.aligned.m8n8.x4.shared.b16 {%0,%1,%2,%3}, [%4];" \
        : "=r"(r0), "=r"(r1), "=r"(r2), "=r"(r3) : "r"(addr))

#define CP_ASYNC16(smem_addr, gptr) \
    asm volatile("cp.async.cg.shared.global [%0], [%1], 16;" \
        :: "r"(smem_addr), "l"(gptr))

#define CP_COMMIT()  asm volatile("cp.async.commit_group;" ::: "memory")
#define CP_WAIT(N)   asm volatile("cp.async.wait_group %0;" :: "n"(N) : "memory")

__device__ __forceinline__ void mma_fp16(float* c, const uint32_t* a, const uint32_t* b) {
    asm volatile(
        "mma.sync.aligned.m16n8k16.row.col.f32.f16.f16.f32 "
        "{%0,%1,%2,%3}, {%4,%5,%6,%7}, {%8,%9}, {%0,%1,%2,%3};"
        : "+f"(c[0]), "+f"(c[1]), "+f"(c[2]), "+f"(c[3])
        : "r"(a[0]), "r"(a[1]), "r"(a[2]), "r"(a[3]), "r"(b[0]), "r"(b[1]));
}

__device__ __forceinline__ uint32_t pack2h(float a, float b) {
    __half2 t = __floats2half2_rn(a, b);
    return *reinterpret_cast<uint32_t*>(&t);
}

// ---------------------------------------------------------------------------
// Scratch
// ---------------------------------------------------------------------------
__device__ __align__(256) __half g_x1[(size_t)M1 * D1];             // X1 fp16
__device__ __align__(256) __half g_x2[(size_t)M1 * D2];             // X2 fp16
__device__ __align__(256) __half g_wt[(size_t)KOUT * D2 * D1];      // W^T fp16 [k][q][p]
__device__ __align__(256) __half g_t[(size_t)M1 * KOUT * D2];       // tmp fp16 [m][k][q]

// ---------------------------------------------------------------------------
// Conversion kernels
// ---------------------------------------------------------------------------
__global__ __launch_bounds__(256) void cvt_fp16_kernel(
    const float* __restrict__ x1, const float* __restrict__ x2, int n4)
{
    int i = blockIdx.x * 256 + threadIdx.x;
    if (i >= n4) return;
    float4 v = reinterpret_cast<const float4*>(x1)[i];
    reinterpret_cast<__half2*>(g_x1)[2 * i] =
        __halves2half2(__float2half_rn(v.x), __float2half_rn(v.y));
    reinterpret_cast<__half2*>(g_x1)[2 * i + 1] =
        __halves2half2(__float2half_rn(v.z), __float2half_rn(v.w));
    float4 w = reinterpret_cast<const float4*>(x2)[i];
    reinterpret_cast<__half2*>(g_x2)[2 * i] =
        __halves2half2(__float2half_rn(w.x), __float2half_rn(w.y));
    reinterpret_cast<__half2*>(g_x2)[2 * i + 1] =
        __halves2half2(__float2half_rn(w.z), __float2half_rn(w.w));
}

// W[k][p][q] -> Wt[k][q][p] fp16.  grid (16,16,64), block (32,8)
__global__ void cvt_w_kernel(const float* __restrict__ W)
{
    __shared__ float t[32][33];
    int k  = blockIdx.z;
    int q0 = blockIdx.x * 32;
    int p0 = blockIdx.y * 32;
    const float* Wk = W + (size_t)k * D1 * D2;
    int tx = threadIdx.x, ty = threadIdx.y;
#pragma unroll
    for (int i = 0; i < 4; i++)
        t[ty + 8 * i][tx] = Wk[(size_t)(p0 + ty + 8 * i) * D2 + q0 + tx];
    __syncthreads();
#pragma unroll
    for (int i = 0; i < 4; i++) {
        size_t o = (size_t)k * D2 * D1 + (size_t)(q0 + ty + 8 * i) * D1 + p0 + tx;
        g_wt[o] = __float2half_rn(t[tx][ty + 8 * i]);
    }
}

// ---------------------------------------------------------------------------
// Tile copy: ROWS rows x 64 halves (128B rows), gmem pitch 512, SW128 smem
// ---------------------------------------------------------------------------
template <int ROWS>
__device__ __forceinline__ void tile_cp64(
    const __half* __restrict__ g, uint32_t s, int tid)
{
#pragma unroll
    for (int idx = tid; idx < ROWS * 8; idx += 256) {
        int row = idx >> 3, u = idx & 7;
        CP_ASYNC16(s + swz128((uint32_t)(row * 128 + u * 16)),
                   g + (size_t)row * 512 + u * 8);
    }
}

// ---------------------------------------------------------------------------
// GEMM1 (R8 best config): tmp[m, kb, q] = sum_p X1[m,p] * W[kb,p,q]
//   grid (4, 4, 64) per batch-pair, block 256 (8 warps), 2 CTAs/SM.
//   Block tile 128(m) x 128(q); warp tile 32x64. K=512 in 8 chunks of 64,
//   3-stage cp.async.
// SMEM stage (32 KB): A(16K) B(16K), SW128.
// ---------------------------------------------------------------------------
#define G1_SLOT 32768
#define G1_SMEM (1024 + 3 * G1_SLOT)   // 99328 -> 2 CTAs/SM

__global__ __launch_bounds__(256, 2) void gemm1_mma(int m_base)
{
    extern __shared__ char smem[];
    uint32_t sb = smem_u32(smem);
    const int tid = threadIdx.x, wid = tid >> 5, lane = tid & 31;
    const int m0 = m_base + blockIdx.x * 128, n0 = blockIdx.y * 128, kb = blockIdx.z;
    const int wm = wid & 3, wn = wid >> 2;       // warp tile 32(m) x 64(n)

    const __half* A = g_x1 + (size_t)m0 * D1;
    const __half* B = g_wt + ((size_t)kb * D2 + n0) * D1;

    float c[2][8][4];
#pragma unroll
    for (int i = 0; i < 2; i++)
#pragma unroll
        for (int j = 0; j < 8; j++)
#pragma unroll
            for (int e = 0; e < 4; e++) c[i][j][e] = 0.0f;

    const int a_r = lane & 15, a_c = (lane >> 4) * 8;
    const int b_r = ((lane >> 4) & 1) * 8 + (lane & 7), b_c = ((lane >> 3) & 1) * 8;

    // prologue: chunks 0,1 -> stages 0,1
#pragma unroll
    for (int s = 0; s < 2; s++) {
        uint32_t tb = sb + 1024 + s * G1_SLOT;
        tile_cp64<128>(A + s * 64, tb, tid);
        tile_cp64<128>(B + s * 64, tb + 16384, tid);
        CP_COMMIT();
    }

#pragma unroll 1
    for (int ch = 0; ch < 8; ch++) {
        if (ch + 2 < 8) { CP_WAIT(1); } else { CP_WAIT(0); }
        __syncthreads();
        if (ch + 2 < 8) {
            int p0 = (ch + 2) * 64;
            uint32_t tb = sb + 1024 + ((ch + 2) % 3) * G1_SLOT;
            tile_cp64<128>(A + p0, tb, tid);
            tile_cp64<128>(B + p0, tb + 16384, tid);
            CP_COMMIT();
        }

        uint32_t tb = sb + 1024 + (ch % 3) * G1_SLOT;
        uint32_t tA = tb, tB = tb + 16384;

#pragma unroll
        for (int kk = 0; kk < 64; kk += 16) {
            uint32_t a[8], b[16];
            LDSM_X4(a[0], a[1], a[2], a[3],
                    tA + swz128((uint32_t)((wm * 32 + a_r) * 128 + (kk + a_c) * 2)));
            LDSM_X4(a[4], a[5], a[6], a[7],
                    tA + swz128((uint32_t)((wm * 32 + 16 + a_r) * 128 + (kk + a_c) * 2)));
#pragma unroll
            for (int q = 0; q < 4; q++)
                LDSM_X4(b[4 * q], b[4 * q + 1], b[4 * q + 2], b[4 * q + 3],
                        tB + swz128((uint32_t)((wn * 64 + q * 16 + b_r) * 128 + (kk + b_c) * 2)));
#pragma unroll
            for (int mt = 0; mt < 2; mt++)
#pragma unroll
                for (int nt = 0; nt < 8; nt++)
                    mma_fp16(c[mt][nt], (mt ? a + 4 : a), b + 2 * nt);
        }
        __syncthreads();
    }

    // ---- Epilogue: stage fp16 in padded SMEM, then coalesced 16B stores
    char* Sh = smem + 1024;                    // [128][pitch 136 half] = 34 KB
#pragma unroll
    for (int mt = 0; mt < 2; mt++)
#pragma unroll
        for (int nt = 0; nt < 8; nt++)
#pragma unroll
            for (int h = 0; h < 2; h++) {
                int m = wm * 32 + mt * 16 + (lane >> 2) + h * 8;
                int n = wn * 64 + nt * 8 + (lane & 3) * 2;
                *reinterpret_cast<uint32_t*>(Sh + m * 272 + n * 2) =
                    pack2h(c[mt][nt][2 * h], c[mt][nt][2 * h + 1]);
            }
    __syncthreads();
#pragma unroll
    for (int idx = tid; idx < 1024; idx += 256) {
        int row = idx >> 3, u = idx & 7;
        size_t ob = (size_t)(m0 + row) * (KOUT * D2) + (size_t)kb * D2 + n0 + u * 16;
        *reinterpret_cast<uint4*>(&g_t[ob]) =
            *reinterpret_cast<const uint4*>(Sh + row * 272 + u * 32);
        *reinterpret_cast<uint4*>(&g_t[ob + 8]) =
            *reinterpret_cast<const uint4*>(Sh + row * 272 + u * 32 + 16);
    }
}

// ---------------------------------------------------------------------------
// GEMM2 (R10 config): out[bi, j, k'] = sum_q X2[b,j,q] * tmp[bi,k',q] + bias
//   grid (512) per batch-pair, block 256 (8 warps), 2 CTAs/SM.
//   Block tile 256(j) x 64(k'); warp tile 64(j) x 32(k').
//   K=512 in 8 chunks of 64, 2-stage cp.async.
// SMEM stage (40 KB): A(32K: 256x64h) B(8K: 64x64h), SW128.
// ---------------------------------------------------------------------------
#define G2_SLOT 40960
#define G2_SMEM (1024 + 2 * G2_SLOT)   // 82944 -> 2 CTAs/SM

__global__ __launch_bounds__(256, 2) void gemm2_mma(
    const float* __restrict__ bias, float* __restrict__ out, int bi_base)
{
    extern __shared__ char smem[];
    uint32_t sb = smem_u32(smem);
    const int tid = threadIdx.x, wid = tid >> 5, lane = tid & 31;
    const int bi = bi_base + blockIdx.x;
    const int b  = bi >> 8;
    const int wm = wid & 3, wn = wid >> 2;       // warp tile 64(j) x 32(k')

    const __half* A = g_x2 + (size_t)b * L_SEQ * D2;
    const __half* B = g_t + (size_t)bi * KOUT * D2;

    float c[4][4][4];
#pragma unroll
    for (int i = 0; i < 4; i++)
#pragma unroll
        for (int j = 0; j < 4; j++)
#pragma unroll
            for (int e = 0; e < 4; e++) c[i][j][e] = 0.0f;

    const int a_r = lane & 15, a_c = (lane >> 4) * 8;
    const int b_r = ((lane >> 4) & 1) * 8 + (lane & 7), b_c = ((lane >> 3) & 1) * 8;

    // prologue: chunk 0 -> stage 0
    {
        uint32_t tb = sb + 1024;
        tile_cp64<256>(A, tb, tid);
        tile_cp64<64>(B, tb + 32768, tid);
        CP_COMMIT();
    }

#pragma unroll 1
    for (int ch = 0; ch < 8; ch++) {
        if (ch < 7) {
            int q0 = (ch + 1) * 64;
            uint32_t tb = sb + 1024 + ((ch + 1) & 1) * G2_SLOT;
            tile_cp64<256>(A + q0, tb, tid);
            tile_cp64<64>(B + q0, tb + 32768, tid);
            CP_COMMIT();
            CP_WAIT(1);
        } else {
            CP_WAIT(0);
        }
        __syncthreads();

        uint32_t tb = sb + 1024 + (ch & 1) * G2_SLOT;
        uint32_t tA = tb, tB = tb + 32768;

#pragma unroll
        for (int kk = 0; kk < 64; kk += 16) {
            uint32_t a[16], bh[8];
#pragma unroll
            for (int q = 0; q < 2; q++)
                LDSM_X4(bh[4 * q], bh[4 * q + 1], bh[4 * q + 2], bh[4 * q + 3],
                        tB + swz128((uint32_t)((wn * 32 + q * 16 + b_r) * 128 + (kk + b_c) * 2)));
#pragma unroll
            for (int mt = 0; mt < 4; mt++)
                LDSM_X4(a[4 * mt], a[4 * mt + 1], a[4 * mt + 2], a[4 * mt + 3],
                        tA + swz128((uint32_t)((wm * 64 + mt * 16 + a_r) * 128 + (kk + a_c) * 2)));
#pragma unroll
            for (int mt = 0; mt < 4; mt++)
#pragma unroll
                for (int nt = 0; nt < 4; nt++)
                    mma_fp16(c[mt][nt], a + 4 * mt, bh + 2 * nt);
        }
        __syncthreads();
    }

    // ---- Epilogue: direct f32 stores + bias
#pragma unroll
    for (int mt = 0; mt < 4; mt++)
#pragma unroll
        for (int nt = 0; nt < 4; nt++) {
            int n = wn * 32 + nt * 8 + (lane & 3) * 2;
            float2 bv = *reinterpret_cast<const float2*>(&bias[n]);
#pragma unroll
            for (int h = 0; h < 2; h++) {
                int m = wm * 64 + mt * 16 + (lane >> 2) + h * 8;
                size_t ob = ((size_t)bi * L_SEQ + m) * KOUT + n;
                float2 v;
                v.x = c[mt][nt][2 * h]     + bv.x;
                v.y = c[mt][nt][2 * h + 1] + bv.y;
                *reinterpret_cast<float2*>(&out[ob]) = v;
            }
        }
}

// ---------------------------------------------------------------------------
// Launch: 4 batch-pairs, interleaved gemm1/gemm2 so each pair's tmp slice
// (33.5 MB) plus W (64 MB) stays L2-resident when gemm2 consumes it.
// ---------------------------------------------------------------------------
extern "C" void kernel_launch(void* const* d_in, const int* in_sizes, int n_in,
                              void* d_out, int out_size)
{
    const float* x1   = (const float*)d_in[0];   // [8,256,512]
    const float* x2   = (const float*)d_in[1];   // [8,256,512]
    const float* w    = (const float*)d_in[2];   // [64,512,512]
    const float* bias = (const float*)d_in[3];   // [64]
    float* out = (float*)d_out;                  // [8,256,256,64]

    cudaFuncSetAttribute(gemm1_mma, cudaFuncAttributeMaxDynamicSharedMemorySize, G1_SMEM);
    cudaFuncSetAttribute(gemm2_mma, cudaFuncAttributeMaxDynamicSharedMemorySize, G2_SMEM);

    int n4 = M1 * D1 / 4;
    cvt_fp16_kernel<<<(n4 + 255) / 256, 256>>>(x1, x2, n4);
    cvt_w_kernel<<<dim3(16, 16, 64), dim3(32, 8)>>>(w);

    // 4 pairs of (gemm1 slice, gemm2 slice); each slice covers 512 bi rows
    for (int p = 0; p < 4; p++) {
        gemm1_mma<<<dim3(4, 4, 64), 256, G1_SMEM>>>(p * 512);
        gemm2_mma<<<512, 256, G2_SMEM>>>(bias, out, p * 512);
    }
}

// round 13
// speedup vs baseline: 1.1141x; 1.1141x over previous
#include <cuda_runtime.h>
#include <cuda_fp16.h>
#include <cstdint>

// ---------------------------------------------------------------------------
// Problem dims
// ---------------------------------------------------------------------------
#define B_BATCH 8
#define L_SEQ   256
#define D1      512
#define D2      512
#define KOUT    64
#define M1      (B_BATCH * L_SEQ)   // 2048 rows (b,i)

// ---------------------------------------------------------------------------
// Helpers (sm_80-era ISA only — harness PTX target is sm_103 without 'a')
// ---------------------------------------------------------------------------
__device__ __forceinline__ uint32_t smem_u32(const void* p) {
    uint32_t a;
    asm("{ .reg .u64 t; cvta.to.shared.u64 t, %1; cvt.u32.u64 %0, t; }"
        : "=r"(a) : "l"(p));
    return a;
}

__device__ __forceinline__ uint32_t swz128(uint32_t off) {  // 128B-row swizzle
    return off ^ ((off >> 3) & 0x70);
}

#define LDSM_X4(r0, r1, r2, r3, addr) \
    asm volatile("ldmatrix.sync.aligned.m8n8.x4.shared.b16 {%0,%1,%2,%3}, [%4];" \
        : "=r"(r0), "=r"(r1), "=r"(r2), "=r"(r3) : "r"(addr))

#define CP_ASYNC16(smem_addr, gptr) \
    asm volatile("cp.async.cg.shared.global [%0], [%1], 16;" \
        :: "r"(smem_addr), "l"(gptr))

#define CP_COMMIT()  asm volatile("cp.async.commit_group;" ::: "memory")
#define CP_WAIT(N)   asm volatile("cp.async.wait_group %0;" :: "n"(N) : "memory")

__device__ __forceinline__ void mma_fp16(float* c, const uint32_t* a, const uint32_t* b) {
    asm volatile(
        "mma.sync.aligned.m16n8k16.row.col.f32.f16.f16.f32 "
        "{%0,%1,%2,%3}, {%4,%5,%6,%7}, {%8,%9}, {%0,%1,%2,%3};"
        : "+f"(c[0]), "+f"(c[1]), "+f"(c[2]), "+f"(c[3])
        : "r"(a[0]), "r"(a[1]), "r"(a[2]), "r"(a[3]), "r"(b[0]), "r"(b[1]));
}

__device__ __forceinline__ uint32_t pack2h(float a, float b) {
    __half2 t = __floats2half2_rn(a, b);
    return *reinterpret_cast<uint32_t*>(&t);
}

// ---------------------------------------------------------------------------
// Scratch
// ---------------------------------------------------------------------------
__device__ __align__(256) __half g_x1[(size_t)M1 * D1];             // X1 fp16
__device__ __align__(256) __half g_x2[(size_t)M1 * D2];             // X2 fp16
__device__ __align__(256) __half g_wt[(size_t)KOUT * D2 * D1];      // W^T fp16 [k][q][p]
__device__ __align__(256) __half g_t[(size_t)M1 * KOUT * D2];       // tmp fp16 [m][k][q]

// ---------------------------------------------------------------------------
// Conversion kernels
// ---------------------------------------------------------------------------
__global__ __launch_bounds__(256) void cvt_fp16_kernel(
    const float* __restrict__ x1, const float* __restrict__ x2, int n4)
{
    int i = blockIdx.x * 256 + threadIdx.x;
    if (i >= n4) return;
    float4 v = reinterpret_cast<const float4*>(x1)[i];
    reinterpret_cast<__half2*>(g_x1)[2 * i] =
        __halves2half2(__float2half_rn(v.x), __float2half_rn(v.y));
    reinterpret_cast<__half2*>(g_x1)[2 * i + 1] =
        __halves2half2(__float2half_rn(v.z), __float2half_rn(v.w));
    float4 w = reinterpret_cast<const float4*>(x2)[i];
    reinterpret_cast<__half2*>(g_x2)[2 * i] =
        __halves2half2(__float2half_rn(w.x), __float2half_rn(w.y));
    reinterpret_cast<__half2*>(g_x2)[2 * i + 1] =
        __halves2half2(__float2half_rn(w.z), __float2half_rn(w.w));
}

// W[k][p][q] -> Wt[k][q][p] fp16.  grid (16,16,64), block (32,8)
__global__ void cvt_w_kernel(const float* __restrict__ W)
{
    __shared__ float t[32][33];
    int k  = blockIdx.z;
    int q0 = blockIdx.x * 32;
    int p0 = blockIdx.y * 32;
    const float* Wk = W + (size_t)k * D1 * D2;
    int tx = threadIdx.x, ty = threadIdx.y;
#pragma unroll
    for (int i = 0; i < 4; i++)
        t[ty + 8 * i][tx] = Wk[(size_t)(p0 + ty + 8 * i) * D2 + q0 + tx];
    __syncthreads();
#pragma unroll
    for (int i = 0; i < 4; i++) {
        size_t o = (size_t)k * D2 * D1 + (size_t)(q0 + ty + 8 * i) * D1 + p0 + tx;
        g_wt[o] = __float2half_rn(t[tx][ty + 8 * i]);
    }
}

// ---------------------------------------------------------------------------
// Tile copy: ROWS rows x 64 halves (128B rows), gmem pitch 512, SW128 smem
// ---------------------------------------------------------------------------
template <int ROWS>
__device__ __forceinline__ void tile_cp64(
    const __half* __restrict__ g, uint32_t s, int tid)
{
#pragma unroll
    for (int idx = tid; idx < ROWS * 8; idx += 256) {
        int row = idx >> 3, u = idx & 7;
        CP_ASYNC16(s + swz128((uint32_t)(row * 128 + u * 16)),
                   g + (size_t)row * 512 + u * 8);
    }
}

// ---------------------------------------------------------------------------
// GEMM1 (best measured config, R8): tmp[m, kb, q] = sum_p X1[m,p] * W[kb,p,q]
//   grid (16, 4, 64), block 256 (8 warps), 2 CTAs/SM.
//   Block tile 128(m) x 128(q); warp tile 32x64. K=512 in 8 chunks of 64,
//   3-stage cp.async.
// SMEM stage (32 KB): A(16K) B(16K), SW128.
// ---------------------------------------------------------------------------
#define G1_SLOT 32768
#define G1_SMEM (1024 + 3 * G1_SLOT)   // 99328 -> 2 CTAs/SM

__global__ __launch_bounds__(256, 2) void gemm1_mma(void)
{
    extern __shared__ char smem[];
    uint32_t sb = smem_u32(smem);
    const int tid = threadIdx.x, wid = tid >> 5, lane = tid & 31;
    const int m0 = blockIdx.x * 128, n0 = blockIdx.y * 128, kb = blockIdx.z;
    const int wm = wid & 3, wn = wid >> 2;       // warp tile 32(m) x 64(n)

    const __half* A = g_x1 + (size_t)m0 * D1;
    const __half* B = g_wt + ((size_t)kb * D2 + n0) * D1;

    float c[2][8][4];
#pragma unroll
    for (int i = 0; i < 2; i++)
#pragma unroll
        for (int j = 0; j < 8; j++)
#pragma unroll
            for (int e = 0; e < 4; e++) c[i][j][e] = 0.0f;

    const int a_r = lane & 15, a_c = (lane >> 4) * 8;
    const int b_r = ((lane >> 4) & 1) * 8 + (lane & 7), b_c = ((lane >> 3) & 1) * 8;

    // prologue: chunks 0,1 -> stages 0,1
#pragma unroll
    for (int s = 0; s < 2; s++) {
        uint32_t tb = sb + 1024 + s * G1_SLOT;
        tile_cp64<128>(A + s * 64, tb, tid);
        tile_cp64<128>(B + s * 64, tb + 16384, tid);
        CP_COMMIT();
    }

#pragma unroll 1
    for (int ch = 0; ch < 8; ch++) {
        if (ch + 2 < 8) { CP_WAIT(1); } else { CP_WAIT(0); }
        __syncthreads();
        if (ch + 2 < 8) {
            int p0 = (ch + 2) * 64;
            uint32_t tb = sb + 1024 + ((ch + 2) % 3) * G1_SLOT;
            tile_cp64<128>(A + p0, tb, tid);
            tile_cp64<128>(B + p0, tb + 16384, tid);
            CP_COMMIT();
        }

        uint32_t tb = sb + 1024 + (ch % 3) * G1_SLOT;
        uint32_t tA = tb, tB = tb + 16384;

#pragma unroll
        for (int kk = 0; kk < 64; kk += 16) {
            uint32_t a[8], b[16];
            LDSM_X4(a[0], a[1], a[2], a[3],
                    tA + swz128((uint32_t)((wm * 32 + a_r) * 128 + (kk + a_c) * 2)));
            LDSM_X4(a[4], a[5], a[6], a[7],
                    tA + swz128((uint32_t)((wm * 32 + 16 + a_r) * 128 + (kk + a_c) * 2)));
#pragma unroll
            for (int q = 0; q < 4; q++)
                LDSM_X4(b[4 * q], b[4 * q + 1], b[4 * q + 2], b[4 * q + 3],
                        tB + swz128((uint32_t)((wn * 64 + q * 16 + b_r) * 128 + (kk + b_c) * 2)));
#pragma unroll
            for (int mt = 0; mt < 2; mt++)
#pragma unroll
                for (int nt = 0; nt < 8; nt++)
                    mma_fp16(c[mt][nt], (mt ? a + 4 : a), b + 2 * nt);
        }
        __syncthreads();
    }

    // ---- Epilogue: stage fp16 in padded SMEM, then coalesced 16B stores
    char* Sh = smem + 1024;                    // [128][pitch 136 half] = 34 KB
#pragma unroll
    for (int mt = 0; mt < 2; mt++)
#pragma unroll
        for (int nt = 0; nt < 8; nt++)
#pragma unroll
            for (int h = 0; h < 2; h++) {
                int m = wm * 32 + mt * 16 + (lane >> 2) + h * 8;
                int n = wn * 64 + nt * 8 + (lane & 3) * 2;
                *reinterpret_cast<uint32_t*>(Sh + m * 272 + n * 2) =
                    pack2h(c[mt][nt][2 * h], c[mt][nt][2 * h + 1]);
            }
    __syncthreads();
#pragma unroll
    for (int idx = tid; idx < 1024; idx += 256) {
        int row = idx >> 3, u = idx & 7;
        size_t ob = (size_t)(m0 + row) * (KOUT * D2) + (size_t)kb * D2 + n0 + u * 16;
        *reinterpret_cast<uint4*>(&g_t[ob]) =
            *reinterpret_cast<const uint4*>(Sh + row * 272 + u * 32);
        *reinterpret_cast<uint4*>(&g_t[ob + 8]) =
            *reinterpret_cast<const uint4*>(Sh + row * 272 + u * 32 + 16);
    }
}

// ---------------------------------------------------------------------------
// GEMM2 (best measured config, R10): out[bi,j,k'] = sum_q X2[b,j,q]*tmp[bi,k',q]
//   + bias[k'].  grid (2048), block 256 (8 warps), 2 CTAs/SM.
//   Block tile 256(j) x 64(k'); warp tile 64(j) x 32(k').
//   K=512 in 8 chunks of 64, 2-stage cp.async.
// SMEM stage (40 KB): A(32K: 256x64h) B(8K: 64x64h), SW128.
// ---------------------------------------------------------------------------
#define G2_SLOT 40960
#define G2_SMEM (1024 + 2 * G2_SLOT)   // 82944 -> 2 CTAs/SM

__global__ __launch_bounds__(256, 2) void gemm2_mma(
    const float* __restrict__ bias, float* __restrict__ out)
{
    extern __shared__ char smem[];
    uint32_t sb = smem_u32(smem);
    const int tid = threadIdx.x, wid = tid >> 5, lane = tid & 31;
    const int bi = blockIdx.x;
    const int b  = bi >> 8;
    const int wm = wid & 3, wn = wid >> 2;       // warp tile 64(j) x 32(k')

    const __half* A = g_x2 + (size_t)b * L_SEQ * D2;
    const __half* B = g_t + (size_t)bi * KOUT * D2;

    float c[4][4][4];
#pragma unroll
    for (int i = 0; i < 4; i++)
#pragma unroll
        for (int j = 0; j < 4; j++)
#pragma unroll
            for (int e = 0; e < 4; e++) c[i][j][e] = 0.0f;

    const int a_r = lane & 15, a_c = (lane >> 4) * 8;
    const int b_r = ((lane >> 4) & 1) * 8 + (lane & 7), b_c = ((lane >> 3) & 1) * 8;

    // prologue: chunk 0 -> stage 0
    {
        uint32_t tb = sb + 1024;
        tile_cp64<256>(A, tb, tid);
        tile_cp64<64>(B, tb + 32768, tid);
        CP_COMMIT();
    }

#pragma unroll 1
    for (int ch = 0; ch < 8; ch++) {
        if (ch < 7) {
            int q0 = (ch + 1) * 64;
            uint32_t tb = sb + 1024 + ((ch + 1) & 1) * G2_SLOT;
            tile_cp64<256>(A + q0, tb, tid);
            tile_cp64<64>(B + q0, tb + 32768, tid);
            CP_COMMIT();
            CP_WAIT(1);
        } else {
            CP_WAIT(0);
        }
        __syncthreads();

        uint32_t tb = sb + 1024 + (ch & 1) * G2_SLOT;
        uint32_t tA = tb, tB = tb + 32768;

#pragma unroll
        for (int kk = 0; kk < 64; kk += 16) {
            uint32_t a[16], bh[8];
#pragma unroll
            for (int q = 0; q < 2; q++)
                LDSM_X4(bh[4 * q], bh[4 * q + 1], bh[4 * q + 2], bh[4 * q + 3],
                        tB + swz128((uint32_t)((wn * 32 + q * 16 + b_r) * 128 + (kk + b_c) * 2)));
#pragma unroll
            for (int mt = 0; mt < 4; mt++)
                LDSM_X4(a[4 * mt], a[4 * mt + 1], a[4 * mt + 2], a[4 * mt + 3],
                        tA + swz128((uint32_t)((wm * 64 + mt * 16 + a_r) * 128 + (kk + a_c) * 2)));
#pragma unroll
            for (int mt = 0; mt < 4; mt++)
#pragma unroll
                for (int nt = 0; nt < 4; nt++)
                    mma_fp16(c[mt][nt], a + 4 * mt, bh + 2 * nt);
        }
        __syncthreads();
    }

    // ---- Epilogue: direct f32 stores + bias
#pragma unroll
    for (int mt = 0; mt < 4; mt++)
#pragma unroll
        for (int nt = 0; nt < 4; nt++) {
            int n = wn * 32 + nt * 8 + (lane & 3) * 2;
            float2 bv = *reinterpret_cast<const float2*>(&bias[n]);
#pragma unroll
            for (int h = 0; h < 2; h++) {
                int m = wm * 64 + mt * 16 + (lane >> 2) + h * 8;
                size_t ob = ((size_t)bi * L_SEQ + m) * KOUT + n;
                float2 v;
                v.x = c[mt][nt][2 * h]     + bv.x;
                v.y = c[mt][nt][2 * h + 1] + bv.y;
                *reinterpret_cast<float2*>(&out[ob]) = v;
            }
        }
}

// ---------------------------------------------------------------------------
// Launch: monolithic (R11's sliced interleave regressed on wave quantization)
// ---------------------------------------------------------------------------
extern "C" void kernel_launch(void* const* d_in, const int* in_sizes, int n_in,
                              void* d_out, int out_size)
{
    const float* x1   = (const float*)d_in[0];   // [8,256,512]
    const float* x2   = (const float*)d_in[1];   // [8,256,512]
    const float* w    = (const float*)d_in[2];   // [64,512,512]
    const float* bias = (const float*)d_in[3];   // [64]
    float* out = (float*)d_out;                  // [8,256,256,64]

    cudaFuncSetAttribute(gemm1_mma, cudaFuncAttributeMaxDynamicSharedMemorySize, G1_SMEM);
    cudaFuncSetAttribute(gemm2_mma, cudaFuncAttributeMaxDynamicSharedMemorySize, G2_SMEM);

    int n4 = M1 * D1 / 4;
    cvt_fp16_kernel<<<(n4 + 255) / 256, 256>>>(x1, x2, n4);
    cvt_w_kernel<<<dim3(16, 16, 64), dim3(32, 8)>>>(w);

    gemm1_mma<<<dim3(16, 4, 64), 256, G1_SMEM>>>();
    gemm2_mma<<<2048, 256, G2_SMEM>>>(bias, out);
}